// round 17
// baseline (speedup 1.0000x reference)
#include <cuda_runtime.h>
#include <cstdint>

#define LL   50
#define DD   64
#define EE   128
#define UU   256
#define NT   256     // 8 warps; 2 CTAs/SM

// ---- smem byte map -------------------------------------------------------
#define OFF_ABIG 0          // A frag big:  [4 mt][8 ks][32 lane][4 u32] = 16384
#define OFF_ASML 16384      // A frag small                               16384
#define OFF_B    32768      // B frags interleaved: [8 ks][32 lanep][68 u32] = 69632
#define OFF_PTR  102400
#define SMEM_BYTES 109952

// pack two f32 -> bf16x2 (lo -> low half, hi -> high half)
#define CVT2(r, lo, hi) asm("cvt.rn.bf16x2.f32 %0, %1, %2;" : "=r"(r) : "f"(hi), "f"(lo))

#define MMA_BF16(D, A, B) \
    asm volatile("mma.sync.aligned.m16n8k16.row.col.f32.bf16.bf16.f32 " \
        "{%0,%1,%2,%3},{%4,%5,%6,%7},{%8,%9},{%0,%1,%2,%3};" \
        : "+f"((D)[0]), "+f"((D)[1]), "+f"((D)[2]), "+f"((D)[3]) \
        : "r"((A).x), "r"((A).y), "r"((A).z), "r"((A).w), "r"((B).x), "r"((B).y))

extern "C" __global__ void __launch_bounds__(NT, 2)
din_fused_kernel(const int*   __restrict__ qid_item,
                 const int*   __restrict__ qid_cate,
                 const int*   __restrict__ sid_item,
                 const int*   __restrict__ sid_cate,
                 const int*   __restrict__ mask,    // bool widened to 4B
                 const float* __restrict__ emb_item,
                 const float* __restrict__ emb_cate,
                 const float* __restrict__ W_hide,
                 const float* __restrict__ b_hide,
                 const float* __restrict__ W_out,
                 const float* __restrict__ b_out,
                 float*       __restrict__ out)
{
    extern __shared__ char smem[];
    uint32_t* Abig = (uint32_t*)(smem + OFF_ABIG);
    uint32_t* Asml = (uint32_t*)(smem + OFF_ASML);
    uint32_t* Bbuf = (uint32_t*)(smem + OFF_B);
    const float** spit = (const float**)(smem + OFF_PTR);  // [56]
    const float** spct = spit + 56;                        // [56]
    float* sq    = (float*)(spct + 56);                    // [128]
    float* sAq   = sq + 128;                               // [8][128]
    float* sAbh  = sAq + 1024;                             // [128]
    float* s_wm  = sAbh + 128;                             // [4][64]
    float* s_sc  = s_wm + 256;                             // [64]
    int* sactive = (int*)(s_sc + 64);                      // [56]
    int* scnt    = sactive + 56;                           // [2]

    const int b    = blockIdx.x;
    const int tid  = threadIdx.x;
    const int warp = tid >> 5;
    const int lane = tid & 31;

    // ---------------- Phase 1: q gather, compaction, row ptrs ----------------
    unsigned bal = 0; bool act = false;
    if (warp < 2) {
        const int l = (warp << 5) + lane;
        act = (l < LL) && (mask[(size_t)b*LL + l] != 0);
        bal = __ballot_sync(0xffffffffu, act);
        if (lane == 0) scnt[warp] = __popc(bal);
    }
    if (tid < EE) {
        const int qi = qid_item[b];
        const int qc = qid_cate[b];
        sq[tid] = (tid < DD) ? emb_item[(size_t)qi*DD + tid]
                             : emb_cate[(size_t)qc*DD + (tid - DD)];
    }
    s_wm[tid] = 0.f;      // NT == 256 == 4*64
    __syncthreads();

    if (warp < 2 && act) {
        const int l   = (warp << 5) + lane;
        const int off = (warp == 1) ? scnt[0] : 0;
        const int pos = off + __popc(bal & ((1u << lane) - 1u));
        sactive[pos] = l;
        spit[pos] = emb_item + (size_t)sid_item[(size_t)b*LL + l]*DD;
        spct[pos] = emb_cate + (size_t)sid_cate[(size_t)b*LL + l]*DD;
    }
    __syncthreads();

    const int nact   = scnt[0] + scnt[1];
    const int mtiles = (nact + 15) >> 4;      // <= 4

    // ---------------- A-fill: k tile -> bf16-split fragments -----------------
    for (int s = tid; s < mtiles*256; s += NT) {
        const int lane2 = s & 31;
        const int ks    = (s >> 5) & 7;
        const int mt    = s >> 8;
        const int g     = lane2 >> 2;
        const int t2    = (lane2 & 3) << 1;
        uint4 big, sml;
        uint32_t* bg = (uint32_t*)&big;
        uint32_t* sm = (uint32_t*)&sml;
        #pragma unroll
        for (int r = 0; r < 4; r++) {
            const int l  = mt*16 + g + ((r & 1) << 3);
            const int dd = ks*16 + t2 + ((r >> 1) << 3);
            float2 v = make_float2(0.f, 0.f);
            if (l < nact) {
                const float* p = (ks < 4) ? spit[l] : spct[l];
                v = *(const float2*)(p + (dd - ((ks < 4) ? 0 : 64)));
            }
            uint32_t B_;
            CVT2(B_, v.x, v.y);
            bg[r] = B_;
            const float rx = v.x - __uint_as_float(B_ << 16);
            const float ry = v.y - __uint_as_float(B_ & 0xffff0000u);
            uint32_t S_;
            CVT2(S_, rx, ry);
            sm[r] = S_;
        }
        const int idx = ((mt*8 + ks)*32 + lane2);
        ((uint4*)Abig)[idx] = big;
        ((uint4*)Asml)[idx] = sml;
    }

    // ================= Two passes over u-halves (128 u each) =================
    #pragma unroll 1
    for (int pass = 0; pass < 2; pass++) {
        // ---- Fold B: W2q = Wk + q*Wp, bf16-split frags (uint4 stores) -------
        // warp = ks; iter i=0..3 handles d-pairs (dA,dA+1) [r=0] and (dB,dB+1) [r=1].
        {
            const int u0 = lane << 2;
            const int gu = (pass << 7) + u0;
            float4 abh = make_float4(0.f, 0.f, 0.f, 0.f);
            #pragma unroll
            for (int i = 0; i < 4; i++) {
                const int dA = warp*16 + 2*i;
                const int dB = dA + 8;
                const float qA0 = sq[dA], qA1 = sq[dA+1];
                const float qB0 = sq[dB], qB1 = sq[dB+1];

                float a0[4], c0[4], a1[4], c1[4];
                {
                    const float4 wk = *(const float4*)(W_hide + (size_t)(128+dA)*UU + gu);
                    const float4 wp = *(const float4*)(W_hide + (size_t)(256+dA)*UU + gu);
                    a0[0]=fmaf(qA0,wp.x,wk.x); a0[1]=fmaf(qA0,wp.y,wk.y);
                    a0[2]=fmaf(qA0,wp.z,wk.z); a0[3]=fmaf(qA0,wp.w,wk.w);
                }
                {
                    const float4 wk = *(const float4*)(W_hide + (size_t)(129+dA)*UU + gu);
                    const float4 wp = *(const float4*)(W_hide + (size_t)(257+dA)*UU + gu);
                    c0[0]=fmaf(qA1,wp.x,wk.x); c0[1]=fmaf(qA1,wp.y,wk.y);
                    c0[2]=fmaf(qA1,wp.z,wk.z); c0[3]=fmaf(qA1,wp.w,wk.w);
                }
                {
                    const float4 wk = *(const float4*)(W_hide + (size_t)(128+dB)*UU + gu);
                    const float4 wp = *(const float4*)(W_hide + (size_t)(256+dB)*UU + gu);
                    a1[0]=fmaf(qB0,wp.x,wk.x); a1[1]=fmaf(qB0,wp.y,wk.y);
                    a1[2]=fmaf(qB0,wp.z,wk.z); a1[3]=fmaf(qB0,wp.w,wk.w);
                }
                {
                    const float4 wk = *(const float4*)(W_hide + (size_t)(129+dB)*UU + gu);
                    const float4 wp = *(const float4*)(W_hide + (size_t)(257+dB)*UU + gu);
                    c1[0]=fmaf(qB1,wp.x,wk.x); c1[1]=fmaf(qB1,wp.y,wk.y);
                    c1[2]=fmaf(qB1,wp.z,wk.z); c1[3]=fmaf(qB1,wp.w,wk.w);
                }
                {
                    const float4 wq0 = *(const float4*)(W_hide + (size_t)dA*UU + gu);
                    const float4 wq1 = *(const float4*)(W_hide + (size_t)(dA+1)*UU + gu);
                    const float4 wq2 = *(const float4*)(W_hide + (size_t)dB*UU + gu);
                    const float4 wq3 = *(const float4*)(W_hide + (size_t)(dB+1)*UU + gu);
                    abh.x = fmaf(qA0,wq0.x, fmaf(qA1,wq1.x, fmaf(qB0,wq2.x, fmaf(qB1,wq3.x, abh.x))));
                    abh.y = fmaf(qA0,wq0.y, fmaf(qA1,wq1.y, fmaf(qB0,wq2.y, fmaf(qB1,wq3.y, abh.y))));
                    abh.z = fmaf(qA0,wq0.z, fmaf(qA1,wq1.z, fmaf(qB0,wq2.z, fmaf(qB1,wq3.z, abh.z))));
                    abh.w = fmaf(qA0,wq0.w, fmaf(qA1,wq1.w, fmaf(qB0,wq2.w, fmaf(qB1,wq3.w, abh.w))));
                }
                #pragma unroll
                for (int cc = 0; cc < 4; cc++) {
                    const int u     = u0 + cc;
                    const int nt    = u >> 3;
                    const int lanep = ((u & 7) << 2) + i;
                    uint4 V;
                    CVT2(V.x, a0[cc], c0[cc]);
                    CVT2(V.y, a1[cc], c1[cc]);
                    {
                        const float rx = a0[cc] - __uint_as_float(V.x << 16);
                        const float ry = c0[cc] - __uint_as_float(V.x & 0xffff0000u);
                        CVT2(V.z, rx, ry);
                    }
                    {
                        const float rx = a1[cc] - __uint_as_float(V.y << 16);
                        const float ry = c1[cc] - __uint_as_float(V.y & 0xffff0000u);
                        CVT2(V.w, rx, ry);
                    }
                    *(uint4*)(Bbuf + warp*2176 + lanep*68 + nt*4) = V;
                }
            }
            *(float4*)(sAq + warp*128 + u0) = abh;
        }
        __syncthreads();
        if (tid < 128) {
            float acc = b_hide[(pass << 7) + tid];
            #pragma unroll
            for (int s = 0; s < 8; s++) acc += sAq[s*128 + tid];
            sAbh[tid] = acc;
        }
        __syncthreads();

        // ---- MMA mainloop: warp = (mtw = w&1) x (nspan = w>>1 -> 4 n8) ------
        {
            const int mtw = warp & 1;
            const int ntb = (warp >> 1) << 2;
            const int g   = lane >> 2;
            const int t2  = (lane & 3) << 1;

            for (int mt = mtw; mt < mtiles; mt += 2) {
                float D[4][4];
                #pragma unroll
                for (int j = 0; j < 4; j++)
                    D[j][0]=D[j][1]=D[j][2]=D[j][3]=0.f;

                #pragma unroll 1
                for (int ks = 0; ks < 8; ks++) {
                    const int aidx = ((mt*8 + ks)*32 + lane);
                    const uint4 Ab = ((const uint4*)Abig)[aidx];
                    const uint4 As = ((const uint4*)Asml)[aidx];
                    #pragma unroll
                    for (int j = 0; j < 4; j++) {
                        const uint4 Bv = *(const uint4*)(Bbuf + ks*2176 + lane*68 + (ntb + j)*4);
                        const uint2 Bb = make_uint2(Bv.x, Bv.y);
                        const uint2 Bs = make_uint2(Bv.z, Bv.w);
                        MMA_BF16(D[j], Ab, Bb);
                        MMA_BF16(D[j], Ab, Bs);
                        MMA_BF16(D[j], As, Bb);
                    }
                }

                // epilogue: + Abh, relu, dot W_out; rows l = mt*16+g, +8
                float sc0 = 0.f, sc1 = 0.f;
                #pragma unroll
                for (int j = 0; j < 4; j++) {
                    const int ul = ((ntb + j) << 3) + t2;
                    const float2 a2 = *(const float2*)(sAbh + ul);
                    const float2 w2 = *(const float2*)(W_out + (pass << 7) + ul);
                    sc0 += fmaxf(D[j][0] + a2.x, 0.f)*w2.x + fmaxf(D[j][1] + a2.y, 0.f)*w2.y;
                    sc1 += fmaxf(D[j][2] + a2.x, 0.f)*w2.x + fmaxf(D[j][3] + a2.y, 0.f)*w2.y;
                }
                sc0 += __shfl_xor_sync(0xffffffffu, sc0, 1);
                sc0 += __shfl_xor_sync(0xffffffffu, sc0, 2);
                sc1 += __shfl_xor_sync(0xffffffffu, sc1, 1);
                sc1 += __shfl_xor_sync(0xffffffffu, sc1, 2);
                if ((lane & 3) == 0) {
                    float* dst = s_wm + ((warp >> 1) << 6);
                    dst[mt*16 + g]     += sc0;
                    dst[mt*16 + g + 8] += sc1;
                }
            }
        }
        __syncthreads();   // B frags reused next pass; s_wm writes visible
    }

    // ---------------- Final: combine scores + weighted sum + store -----------
    if (tid < 64)
        s_sc[tid] = (tid < nact)
            ? (s_wm[tid] + s_wm[64 + tid]) + (s_wm[128 + tid] + s_wm[192 + tid]) + b_out[0]
            : 0.f;
    __syncthreads();

    if (tid < EE) {
        float acc = 0.f;
        for (int i = 0; i < nact; i++) {
            const float kv = (tid < DD) ? spit[i][tid] : spct[i][tid - DD];
            acc = fmaf(s_sc[i], kv, acc);
        }
        out[(size_t)b*EE + tid] = acc;
    }
}

extern "C" void kernel_launch(void* const* d_in, const int* in_sizes, int n_in,
                              void* d_out, int out_size)
{
    const int*   qid_item = (const int*)  d_in[0];
    const int*   qid_cate = (const int*)  d_in[1];
    const int*   sid_item = (const int*)  d_in[2];
    const int*   sid_cate = (const int*)  d_in[3];
    const int*   mask     = (const int*)  d_in[4];
    const float* emb_item = (const float*)d_in[5];
    const float* emb_cate = (const float*)d_in[6];
    const float* W_hide   = (const float*)d_in[7];
    const float* b_hide   = (const float*)d_in[8];
    const float* W_out    = (const float*)d_in[9];
    const float* b_out    = (const float*)d_in[10];
    float*       out      = (float*)      d_out;

    const int B = in_sizes[0];

    cudaFuncSetAttribute(din_fused_kernel,
                         cudaFuncAttributeMaxDynamicSharedMemorySize, SMEM_BYTES);

    din_fused_kernel<<<B, NT, SMEM_BYTES>>>(
        qid_item, qid_cate, sid_item, sid_cate, mask,
        emb_item, emb_cate, W_hide, b_hide, W_out, b_out, out);
}